// round 17
// baseline (speedup 1.0000x reference)
#include <cuda_runtime.h>
#include <cuda_bf16.h>
#include <cuda_fp16.h>
#include <cstdint>

// Problem constants
#define NXg 512
#define NYg 512
#define NSENS 128
#define NT 2048
#define NPIX (NXg * NYg)

// fp16 scratch: [s][t] -> 8 channels x half = 16B entry. 4 MB total.
__device__ uint4 g_scratchH[NSENS * NT];

__device__ __forceinline__ unsigned pack2(float a, float b) {
    __half2 h = __floats2half2_rn(a, b);
    return *(unsigned*)&h;
}
__device__ __forceinline__ __half2 h2(unsigned u) { return *(__half2*)&u; }

__device__ __forceinline__ unsigned long long packf2(float a, float b) {
    unsigned long long r;
    asm("mov.b64 %0, {%1, %2};" : "=l"(r) : "f"(a), "f"(b));
    return r;
}

// ---------------------------------------------------------------------------
// Prep kernel: transpose+quantize sensor_data [B=4][C=2][S=128][T=2048]
// -> [S][T][8ch fp16]. Each thread handles 4 consecutive t.
// ---------------------------------------------------------------------------
__global__ __launch_bounds__(256) void das_transpose_kernel(
    const float* __restrict__ sd)
{
    int idx = blockIdx.x * blockDim.x + threadIdx.x;   // 0 .. 128*512-1
    if (idx >= NSENS * (NT / 4)) return;
    int s  = idx >> 9;
    int tq = (idx & 511) << 2;

    const int bcStride = NSENS * NT;
    const float* base = sd + s * NT + tq;

    float4 c0 = *(const float4*)(base + 0 * bcStride);
    float4 c1 = *(const float4*)(base + 1 * bcStride);
    float4 c2 = *(const float4*)(base + 2 * bcStride);
    float4 c3 = *(const float4*)(base + 3 * bcStride);
    float4 c4 = *(const float4*)(base + 4 * bcStride);
    float4 c5 = *(const float4*)(base + 5 * bcStride);
    float4 c6 = *(const float4*)(base + 6 * bcStride);
    float4 c7 = *(const float4*)(base + 7 * bcStride);

    unsigned e = ((unsigned)s << 11) + (unsigned)tq;

    g_scratchH[e + 0] = make_uint4(pack2(c0.x, c1.x), pack2(c2.x, c3.x),
                                   pack2(c4.x, c5.x), pack2(c6.x, c7.x));
    g_scratchH[e + 1] = make_uint4(pack2(c0.y, c1.y), pack2(c2.y, c3.y),
                                   pack2(c4.y, c5.y), pack2(c6.y, c7.y));
    g_scratchH[e + 2] = make_uint4(pack2(c0.z, c1.z), pack2(c2.z, c3.z),
                                   pack2(c4.z, c5.z), pack2(c6.z, c7.z));
    g_scratchH[e + 3] = make_uint4(pack2(c0.w, c1.w), pack2(c2.w, c3.w),
                                   pack2(c4.w, c5.w), pack2(c6.w, c7.w));
}

// ---------------------------------------------------------------------------
// Main DAS kernel — 2 pixels per thread for ILP.
// Block = 128 threads, tile 16(iy) x 16(ix). Warp patch 8(iy) x 4(ix); each
// thread handles (iy, ix) and (iy, ix+4) — fiy (and the packed dy chain) is
// SHARED between the two pixels. 8 independent LDG.128 in flight per warp
// iteration. Arithmetic per pixel identical to R16 (bit-frozen chain).
// ---------------------------------------------------------------------------
__global__ __launch_bounds__(128) void das_main_kernel(
    const int* __restrict__ sensor_xy,   // [128][2] int32
    float* __restrict__ out)             // [8][NPIX]
{
    // Sensor-pair layout: (cxA, cxB, cyA, cyB) per pair -> 1 LDS.128/pair.
    __shared__ float4 sxyp[NSENS / 2];

    const int tid  = threadIdx.x;        // 0..127
    const int lane = tid & 31;
    const int w    = tid >> 5;           // 0..3

    if (tid < NSENS / 2) {
        int4 q = ((const int4*)sensor_xy)[tid];
        sxyp[tid] = make_float4((float)q.x, (float)q.z, (float)q.y, (float)q.w);
    }
    __syncthreads();

    const int ly = lane & 7;
    const int lx = lane >> 3;            // 0..3
    const int wy = w & 1;
    const int wx = w >> 1;               // 0..1

    const int iy  = blockIdx.x * 16 + wy * 8 + ly;
    const int ix0 = blockIdx.y * 16 + wx * 8 + lx;   // pixel 0
    const int ix1 = ix0 + 4;                          // pixel 1

    const float fiy  = (float)iy;
    const float fix0 = (float)ix0;
    const float fix1 = (float)ix1;

    // XLA chain (bit-exact, validated R3): dis * fl(fl(1/VS)*fl(1/DT)).
    const float K = (1.0f / 1550.0f) * (1.0f / 2.5e-8f);

    const unsigned long long nfiy2  = packf2(-fiy, -fiy);
    const unsigned long long nfix20 = packf2(-fix0, -fix0);
    const unsigned long long nfix21 = packf2(-fix1, -fix1);
    const unsigned long long e4x2   = packf2(1e-4f, 1e-4f);

    // Packed accumulators, per pixel.
    unsigned long long p0a0 = 0ull, p0a1 = 0ull, p0a2 = 0ull, p0a3 = 0ull;
    unsigned long long p1a0 = 0ull, p1a1 = 0ull, p1a2 = 0ull, p1a3 = 0ull;

    #pragma unroll 1
    for (int s = 0; s < NSENS; s += 4) {
        const int k = s >> 1;
        float4 m0 = sxyp[k];       // pair (s, s+1)
        float4 m1 = sxyp[k + 1];   // pair (s+2, s+3)

        unsigned long long xp0 = packf2(m0.x, m0.y);
        unsigned long long yp0 = packf2(m0.z, m0.w);
        unsigned long long xp1 = packf2(m1.x, m1.y);
        unsigned long long yp1 = packf2(m1.z, m1.w);

        // --- shared dy chain (same fiy for both pixels) ---
        unsigned long long dy0, dy1, sy0, sy1;
        asm("add.rn.f32x2 %0, %1, %2;" : "=l"(dy0) : "l"(yp0), "l"(nfiy2));
        asm("add.rn.f32x2 %0, %1, %2;" : "=l"(dy1) : "l"(yp1), "l"(nfiy2));
        asm("mul.rn.f32x2 %0, %0, %1;" : "+l"(dy0) : "l"(e4x2));
        asm("mul.rn.f32x2 %0, %0, %1;" : "+l"(dy1) : "l"(e4x2));
        asm("mul.rn.f32x2 %0, %1, %1;" : "=l"(sy0) : "l"(dy0));
        asm("mul.rn.f32x2 %0, %1, %1;" : "=l"(sy1) : "l"(dy1));

        // --- per-pixel dx chains + r2 ---
        unsigned long long P0dx0, P0dx1, P1dx0, P1dx1;
        asm("add.rn.f32x2 %0, %1, %2;" : "=l"(P0dx0) : "l"(xp0), "l"(nfix20));
        asm("add.rn.f32x2 %0, %1, %2;" : "=l"(P0dx1) : "l"(xp1), "l"(nfix20));
        asm("add.rn.f32x2 %0, %1, %2;" : "=l"(P1dx0) : "l"(xp0), "l"(nfix21));
        asm("add.rn.f32x2 %0, %1, %2;" : "=l"(P1dx1) : "l"(xp1), "l"(nfix21));
        asm("mul.rn.f32x2 %0, %0, %1;" : "+l"(P0dx0) : "l"(e4x2));
        asm("mul.rn.f32x2 %0, %0, %1;" : "+l"(P0dx1) : "l"(e4x2));
        asm("mul.rn.f32x2 %0, %0, %1;" : "+l"(P1dx0) : "l"(e4x2));
        asm("mul.rn.f32x2 %0, %0, %1;" : "+l"(P1dx1) : "l"(e4x2));
        asm("mul.rn.f32x2 %0, %0, %0;" : "+l"(P0dx0));
        asm("mul.rn.f32x2 %0, %0, %0;" : "+l"(P0dx1));
        asm("mul.rn.f32x2 %0, %0, %0;" : "+l"(P1dx0));
        asm("mul.rn.f32x2 %0, %0, %0;" : "+l"(P1dx1));

        unsigned long long P0r0, P0r1, P1r0, P1r1;
        asm("add.rn.f32x2 %0, %1, %2;" : "=l"(P0r0) : "l"(P0dx0), "l"(sy0));
        asm("add.rn.f32x2 %0, %1, %2;" : "=l"(P0r1) : "l"(P0dx1), "l"(sy1));
        asm("add.rn.f32x2 %0, %1, %2;" : "=l"(P1r0) : "l"(P1dx0), "l"(sy0));
        asm("add.rn.f32x2 %0, %1, %2;" : "=l"(P1r1) : "l"(P1dx1), "l"(sy1));

        float rA0, rB0, rC0, rD0, rA1, rB1, rC1, rD1;
        asm("mov.b64 {%0, %1}, %2;" : "=f"(rA0), "=f"(rB0) : "l"(P0r0));
        asm("mov.b64 {%0, %1}, %2;" : "=f"(rC0), "=f"(rD0) : "l"(P0r1));
        asm("mov.b64 {%0, %1}, %2;" : "=f"(rA1), "=f"(rB1) : "l"(P1r0));
        asm("mov.b64 {%0, %1}, %2;" : "=f"(rC1), "=f"(rD1) : "l"(P1r1));

        int tA0 = (int)__fmul_rn(__fsqrt_rn(rA0), K);
        int tB0 = (int)__fmul_rn(__fsqrt_rn(rB0), K);
        int tC0 = (int)__fmul_rn(__fsqrt_rn(rC0), K);
        int tD0 = (int)__fmul_rn(__fsqrt_rn(rD0), K);
        int tA1 = (int)__fmul_rn(__fsqrt_rn(rA1), K);
        int tB1 = (int)__fmul_rn(__fsqrt_rn(rB1), K);
        int tC1 = (int)__fmul_rn(__fsqrt_rn(rC1), K);
        int tD1 = (int)__fmul_rn(__fsqrt_rn(rD1), K);

        uint4 vA0 = __ldg(&g_scratchH[(((unsigned)(s + 0)) << 11) + (unsigned)tA0]);
        uint4 vB0 = __ldg(&g_scratchH[(((unsigned)(s + 1)) << 11) + (unsigned)tB0]);
        uint4 vC0 = __ldg(&g_scratchH[(((unsigned)(s + 2)) << 11) + (unsigned)tC0]);
        uint4 vD0 = __ldg(&g_scratchH[(((unsigned)(s + 3)) << 11) + (unsigned)tD0]);
        uint4 vA1 = __ldg(&g_scratchH[(((unsigned)(s + 0)) << 11) + (unsigned)tA1]);
        uint4 vB1 = __ldg(&g_scratchH[(((unsigned)(s + 1)) << 11) + (unsigned)tB1]);
        uint4 vC1 = __ldg(&g_scratchH[(((unsigned)(s + 2)) << 11) + (unsigned)tC1]);
        uint4 vD1 = __ldg(&g_scratchH[(((unsigned)(s + 3)) << 11) + (unsigned)tD1]);

        // --- pixel 0: quad HADD2 tree (R15-validated), convert, accumulate ---
        {
            __half2 q0 = __hadd2(__hadd2(h2(vA0.x), h2(vB0.x)), __hadd2(h2(vC0.x), h2(vD0.x)));
            __half2 q1 = __hadd2(__hadd2(h2(vA0.y), h2(vB0.y)), __hadd2(h2(vC0.y), h2(vD0.y)));
            __half2 q2 = __hadd2(__hadd2(h2(vA0.z), h2(vB0.z)), __hadd2(h2(vC0.z), h2(vD0.z)));
            __half2 q3 = __hadd2(__hadd2(h2(vA0.w), h2(vB0.w)), __hadd2(h2(vC0.w), h2(vD0.w)));
            float2 f01 = __half22float2(q0);
            float2 f23 = __half22float2(q1);
            float2 f45 = __half22float2(q2);
            float2 f67 = __half22float2(q3);
            unsigned long long u01 = packf2(f01.x, f01.y);
            unsigned long long u23 = packf2(f23.x, f23.y);
            unsigned long long u45 = packf2(f45.x, f45.y);
            unsigned long long u67 = packf2(f67.x, f67.y);
            asm("add.rn.f32x2 %0, %0, %1;" : "+l"(p0a0) : "l"(u01));
            asm("add.rn.f32x2 %0, %0, %1;" : "+l"(p0a1) : "l"(u23));
            asm("add.rn.f32x2 %0, %0, %1;" : "+l"(p0a2) : "l"(u45));
            asm("add.rn.f32x2 %0, %0, %1;" : "+l"(p0a3) : "l"(u67));
        }
        // --- pixel 1 ---
        {
            __half2 q0 = __hadd2(__hadd2(h2(vA1.x), h2(vB1.x)), __hadd2(h2(vC1.x), h2(vD1.x)));
            __half2 q1 = __hadd2(__hadd2(h2(vA1.y), h2(vB1.y)), __hadd2(h2(vC1.y), h2(vD1.y)));
            __half2 q2 = __hadd2(__hadd2(h2(vA1.z), h2(vB1.z)), __hadd2(h2(vC1.z), h2(vD1.z)));
            __half2 q3 = __hadd2(__hadd2(h2(vA1.w), h2(vB1.w)), __hadd2(h2(vC1.w), h2(vD1.w)));
            float2 f01 = __half22float2(q0);
            float2 f23 = __half22float2(q1);
            float2 f45 = __half22float2(q2);
            float2 f67 = __half22float2(q3);
            unsigned long long u01 = packf2(f01.x, f01.y);
            unsigned long long u23 = packf2(f23.x, f23.y);
            unsigned long long u45 = packf2(f45.x, f45.y);
            unsigned long long u67 = packf2(f67.x, f67.y);
            asm("add.rn.f32x2 %0, %0, %1;" : "+l"(p1a0) : "l"(u01));
            asm("add.rn.f32x2 %0, %0, %1;" : "+l"(p1a1) : "l"(u23));
            asm("add.rn.f32x2 %0, %0, %1;" : "+l"(p1a2) : "l"(u45));
            asm("add.rn.f32x2 %0, %0, %1;" : "+l"(p1a3) : "l"(u67));
        }
    }

    unsigned lo, hi;
    {
        const int p = ix0 * NYg + iy;
        asm("mov.b64 {%0,%1}, %2;" : "=r"(lo), "=r"(hi) : "l"(p0a0));
        out[0 * NPIX + p] = __uint_as_float(lo);
        out[1 * NPIX + p] = __uint_as_float(hi);
        asm("mov.b64 {%0,%1}, %2;" : "=r"(lo), "=r"(hi) : "l"(p0a1));
        out[2 * NPIX + p] = __uint_as_float(lo);
        out[3 * NPIX + p] = __uint_as_float(hi);
        asm("mov.b64 {%0,%1}, %2;" : "=r"(lo), "=r"(hi) : "l"(p0a2));
        out[4 * NPIX + p] = __uint_as_float(lo);
        out[5 * NPIX + p] = __uint_as_float(hi);
        asm("mov.b64 {%0,%1}, %2;" : "=r"(lo), "=r"(hi) : "l"(p0a3));
        out[6 * NPIX + p] = __uint_as_float(lo);
        out[7 * NPIX + p] = __uint_as_float(hi);
    }
    {
        const int p = ix1 * NYg + iy;
        asm("mov.b64 {%0,%1}, %2;" : "=r"(lo), "=r"(hi) : "l"(p1a0));
        out[0 * NPIX + p] = __uint_as_float(lo);
        out[1 * NPIX + p] = __uint_as_float(hi);
        asm("mov.b64 {%0,%1}, %2;" : "=r"(lo), "=r"(hi) : "l"(p1a1));
        out[2 * NPIX + p] = __uint_as_float(lo);
        out[3 * NPIX + p] = __uint_as_float(hi);
        asm("mov.b64 {%0,%1}, %2;" : "=r"(lo), "=r"(hi) : "l"(p1a2));
        out[4 * NPIX + p] = __uint_as_float(lo);
        out[5 * NPIX + p] = __uint_as_float(hi);
        asm("mov.b64 {%0,%1}, %2;" : "=r"(lo), "=r"(hi) : "l"(p1a3));
        out[6 * NPIX + p] = __uint_as_float(lo);
        out[7 * NPIX + p] = __uint_as_float(hi);
    }
}

// ---------------------------------------------------------------------------
// Entry point
// ---------------------------------------------------------------------------
extern "C" void kernel_launch(void* const* d_in, const int* in_sizes, int n_in,
                              void* d_out, int out_size)
{
    const float* sensor_data = (const float*)d_in[0];   // (4,2,128,2048) f32
    const int*   sensor_xy   = (const int*)d_in[1];     // (128,2) i32
    float*       out         = (float*)d_out;           // (4,2,512,512) f32

    das_transpose_kernel<<<(NSENS * (NT / 4) + 255) / 256, 256>>>(sensor_data);

    dim3 block(128);
    dim3 grid(NYg / 16, NXg / 16);
    das_main_kernel<<<grid, block>>>(sensor_xy, out);
}